// round 5
// baseline (speedup 1.0000x reference)
#include <cuda_runtime.h>
#include <cuda_bf16.h>
#include <cstdint>

#define K_H  128
#define K_W  128
#define K_HW 16384
#define K_B  4
#define K_NS 33

// ======================= device scratch (static, no alloc) =======================
__device__ __align__(16) __nv_bfloat16 g_a1h[(size_t)K_B*K_HW*576];
__device__ __align__(16) __nv_bfloat16 g_a1l[(size_t)K_B*K_HW*576];
__device__ __align__(16) __nv_bfloat16 g_a2h[(size_t)K_B*K_HW*256];
__device__ __align__(16) __nv_bfloat16 g_a2l[(size_t)K_B*K_HW*256];
__device__ __align__(16) __nv_bfloat16 g_a3h[(size_t)K_B*K_HW*128];
__device__ __align__(16) __nv_bfloat16 g_a3l[(size_t)K_B*K_HW*128];
__device__ __align__(16) float g_y1[(size_t)K_B*K_HW*256];
__device__ __align__(16) float g_y2[(size_t)K_B*K_HW*128];
__device__ __align__(16) float g_y3[(size_t)K_B*K_HW*64];
__device__ __align__(16) __nv_bfloat16 g_w1h[9*256*576];
__device__ __align__(16) __nv_bfloat16 g_w1l[9*256*576];
__device__ __align__(16) __nv_bfloat16 g_w2h[9*128*256];
__device__ __align__(16) __nv_bfloat16 g_w2l[9*128*256];
__device__ __align__(16) __nv_bfloat16 g_w3h[9*64*128];
__device__ __align__(16) __nv_bfloat16 g_w3l[9*64*128];
__device__ float g_gs[3][64], g_gq[3][64];
__device__ float g_sct1[K_B*256*2], g_sct2[K_B*128*2], g_sct3[K_B*64*2];
__device__ float g_psum[K_B*K_NS*64];
__device__ float g_pcnt[K_B*K_NS];

// ======================= helpers =======================
__device__ __forceinline__ uint32_t smem_u32(const void* p) {
    uint32_t a;
    asm("{ .reg .u64 t; cvta.to.shared.u64 t, %1; cvt.u32.u64 %0, t; }" : "=r"(a) : "l"(p));
    return a;
}
__device__ __forceinline__ void cp16(uint32_t dst, const void* src, uint32_t sz){
    asm volatile("cp.async.cg.shared.global [%0], [%1], 16, %2;" :: "r"(dst), "l"(src), "r"(sz));
}
#define CP_COMMIT() asm volatile("cp.async.commit_group;" ::: "memory")
#define CP_WAIT1()  asm volatile("cp.async.wait_group 1;"  ::: "memory")
__device__ __forceinline__ void ldsm4(uint32_t (&r)[4], uint32_t a){
    asm volatile("ldmatrix.sync.aligned.m8n8.x4.shared.b16 {%0,%1,%2,%3}, [%4];"
        : "=r"(r[0]), "=r"(r[1]), "=r"(r[2]), "=r"(r[3]) : "r"(a));
}
__device__ __forceinline__ void mma16816(float (&d)[4], const uint32_t (&a)[4],
                                         uint32_t b0, uint32_t b1){
    asm volatile(
        "mma.sync.aligned.m16n8k16.row.col.f32.bf16.bf16.f32 "
        "{%0,%1,%2,%3},{%4,%5,%6,%7},{%8,%9},{%0,%1,%2,%3};"
        : "+f"(d[0]), "+f"(d[1]), "+f"(d[2]), "+f"(d[3])
        : "r"(a[0]), "r"(a[1]), "r"(a[2]), "r"(a[3]), "r"(b0), "r"(b1));
}
__device__ __forceinline__ void split_hl(float v, __nv_bfloat16& h, __nv_bfloat16& l){
    h = __float2bfloat16(v);
    l = __float2bfloat16(v - __bfloat162float(h));
}

// ======================= small kernels =======================
__global__ void zero_bufs(){
    int i = blockIdx.x*256 + threadIdx.x;
    if (i < K_B*K_NS*64) g_psum[i] = 0.f;
    if (i < K_B*K_NS)    g_pcnt[i] = 0.f;
    if (i < 64){
        g_gs[0][i]=0.f; g_gs[1][i]=0.f; g_gs[2][i]=0.f;
        g_gq[0][i]=0.f; g_gq[1][i]=0.f; g_gq[2][i]=0.f;
    }
}

template<int LAYER>
__global__ void repack_w(const float* __restrict__ w){
    constexpr int Cin  = (LAYER==1)?576:(LAYER==2)?256:128;
    constexpr int Cout = (LAYER==1)?256:(LAYER==2)?128:64;
    __nv_bfloat16* wh = (LAYER==1)?g_w1h:(LAYER==2)?g_w2h:g_w3h;
    __nv_bfloat16* wl = (LAYER==1)?g_w1l:(LAYER==2)?g_w2l:g_w3l;
    int n = Cout*Cin*9;
    for (int i = blockIdx.x*blockDim.x + threadIdx.x; i < n; i += gridDim.x*blockDim.x){
        int k  = i % 9;
        int t  = i / 9;
        int ci = t % Cin;
        int co = t / Cin;
        __nv_bfloat16 h, l;
        split_hl(w[i], h, l);
        size_t o = ((size_t)k*Cout + co)*Cin + ci;
        wh[o] = h; wl[o] = l;
    }
}

__global__ void xform1(const float* __restrict__ x, const float* __restrict__ wc,
                       const float* __restrict__ bc){
    __shared__ float tile[64][129];
    int cblk = blockIdx.x, h = blockIdx.y, b = blockIdx.z, tid = threadIdx.x;
    if (cblk < 8){
        for (int i = tid; i < 64*128; i += 256){
            int ci = i >> 7, w = i & 127;
            tile[ci][w] = x[(((size_t)b*512 + cblk*64 + ci)*K_H + h)*K_W + w];
        }
    } else {
        for (int i = tid; i < 64*128; i += 256){
            int ci = i >> 7, w = i & 127;
            tile[ci][w] = fmaxf(wc[2*ci]*(float)w + wc[2*ci+1]*(float)h + bc[ci], 0.f);
        }
    }
    __syncthreads();
    for (int i = tid; i < 64*128; i += 256){
        int px = i >> 6, c = i & 63;
        __nv_bfloat16 hv, lv;
        split_hl(tile[c][px], hv, lv);
        size_t o = (((size_t)b*K_H + h)*K_W + px)*576 + cblk*64 + c;
        g_a1h[o] = hv; g_a1l[o] = lv;
    }
}

template<int L>
__global__ void act_xform(){
    constexpr int C = (L==2)?256:128;
    const float* __restrict__ y   = (L==2)?g_y1:g_y2;
    const float* __restrict__ sct = (L==2)?g_sct1:g_sct2;
    __nv_bfloat16* __restrict__ ah = (L==2)?g_a2h:g_a3h;
    __nv_bfloat16* __restrict__ al = (L==2)?g_a2l:g_a3l;
    size_t idx = (size_t)blockIdx.x*256 + threadIdx.x;
    if (idx >= (size_t)K_B*K_HW*C) return;
    int c = (int)(idx % C);
    int b = (int)(idx / ((size_t)K_HW*C));
    float2 st = ((const float2*)sct)[b*C + c];
    float v = fmaxf(fmaf(st.x, y[idx], st.y), 0.f);
    __nv_bfloat16 hv, lv;
    split_hl(v, hv, lv);
    ah[idx] = hv; al[idx] = lv;
}

// ======================= conv3x3 via mma.sync bf16x3 + cp.async =======================
// Loads for chunk cc+2 are issued BEFORE compute of chunk cc (2-chunk latency cover).
template<int LAYER>
__global__ void __launch_bounds__(256,2)
conv_hmma(const float* __restrict__ bias){
    constexpr int Cin  = (LAYER==1)?576:(LAYER==2)?256:128;
    constexpr int Cout = (LAYER==1)?256:(LAYER==2)?128:64;
    constexpr int BN   = (Cout>=128)?128:64;
    constexpr int NCB  = Cin/32;
    constexpr int NC   = 9*NCB;
    constexpr int NI   = BN/16;
    constexpr int BIT  = BN/64;
    constexpr int APL  = 10496;
    constexpr int BPL  = BN*80;
    constexpr int ABYT = 4*APL;

    const __nv_bfloat16* __restrict__ act_h = (LAYER==1)?g_a1h:(LAYER==2)?g_a2h:g_a3h;
    const __nv_bfloat16* __restrict__ act_l = (LAYER==1)?g_a1l:(LAYER==2)?g_a2l:g_a3l;
    const __nv_bfloat16* __restrict__ w_h   = (LAYER==1)?g_w1h:(LAYER==2)?g_w2h:g_w3h;
    const __nv_bfloat16* __restrict__ w_l   = (LAYER==1)?g_w1l:(LAYER==2)?g_w2l:g_w3l;
    float* __restrict__ out = (LAYER==1)?g_y1:(LAYER==2)?g_y2:g_y3;

    extern __shared__ __align__(128) char dsm[];
    const uint32_t sbase = smem_u32(dsm);

    const int tid  = threadIdx.x;
    const int lane = tid & 31;
    const int wm   = (tid >> 5) & 3;
    const int wn   = tid >> 7;
    const int h    = blockIdx.x;
    const int b    = blockIdx.y;
    const int cob  = blockIdx.z*BN;

    if (tid < 160){
        int pl = tid/40, rem = tid%40;
        uint32_t row = (rem >= 20) ? 129u : 0u;
        *(uint32_t*)(dsm + pl*APL + row*80 + (rem%20)*4) = 0u;
    }

    float acc[2][NI][4];
    #pragma unroll
    for (int mi=0;mi<2;mi++)
        #pragma unroll
        for (int ni=0;ni<NI;ni++)
            #pragma unroll
            for (int j=0;j<4;j++) acc[mi][ni][j] = 0.f;

#define ALOAD(G) { \
        const int g_ = (G); \
        const int ky_ = g_/NCB, cbk_ = g_ - ky_*NCB; \
        const int hh_ = h + ky_ - 1; \
        const uint32_t sz_ = (hh_>=0 && hh_<K_H) ? 16u : 0u; \
        const int hc_ = hh_<0?0:(hh_>127?127:hh_); \
        const size_t so_ = ((size_t)(b*K_H + hc_)*K_W)*Cin + cbk_*32; \
        const __nv_bfloat16* sh_ = act_h + so_; \
        const __nv_bfloat16* sl_ = act_l + so_; \
        const uint32_t db_ = sbase + (uint32_t)((g_&1)*2)*APL; \
        _Pragma("unroll") \
        for (int it = 0; it < 2; it++){ \
            int idx_ = it*256 + tid, r_ = idx_>>2, q_ = idx_&3; \
            uint32_t d_ = db_ + (r_+1)*80 + q_*16; \
            const size_t off_ = (size_t)r_*Cin + q_*8; \
            cp16(d_,        sh_ + off_, sz_); \
            cp16(d_ + APL,  sl_ + off_, sz_); \
        } }

#define BLOAD(CC) { \
        const int cc_ = (CC); \
        const int g_ = cc_/3, kx_ = cc_ - g_*3; \
        const int k_ = (g_/NCB)*3 + kx_, cbk_ = g_%NCB; \
        const size_t so_ = ((size_t)(k_*Cout + cob))*Cin + cbk_*32; \
        const __nv_bfloat16* sh_ = w_h + so_; \
        const __nv_bfloat16* sl_ = w_l + so_; \
        const uint32_t db_ = sbase + ABYT + (uint32_t)(kx_*2)*BPL; \
        _Pragma("unroll") \
        for (int it = 0; it < BIT; it++){ \
            int idx_ = it*256 + tid, r_ = idx_>>2, q_ = idx_&3; \
            uint32_t d_ = db_ + r_*80 + q_*16; \
            const size_t off_ = (size_t)r_*Cin + q_*8; \
            cp16(d_,        sh_ + off_, 16u); \
            cp16(d_ + BPL,  sl_ + off_, 16u); \
        } }

    const uint32_t aoff0 = (uint32_t)((wm*32 + (lane & 15))*80 + (lane >> 4)*16);
    const uint32_t boff  = (uint32_t)((wn*(BN/2) + (lane & 15))*80 + (lane >> 4)*16);

    // prologue: chunk0 (A g0 + B0), chunk1 (B1)
    ALOAD(0); BLOAD(0); CP_COMMIT();
    BLOAD(1); CP_COMMIT();

    #pragma unroll 1
    for (int cc = 0; cc < NC; ++cc){
        const int g  = cc/3;
        const int kx = cc - g*3;
        CP_WAIT1();           // chunk cc complete (cc+1 may remain in flight)
        __syncthreads();      // publish + all warps past chunk cc-1

        // issue loads for chunk cc+2 BEFORE compute => ~2 chunks of latency cover
        if (cc + 2 < NC){
            BLOAD(cc + 2);
            if ((cc + 2) % 3 == 0) ALOAD((cc + 2)/3);
        }
        CP_COMMIT();

        const uint32_t Ab = sbase + (uint32_t)((g&1)*2)*APL;
        const uint32_t Bb = sbase + ABYT + (uint32_t)(kx*2)*BPL;
        const uint32_t ao = aoff0 + (uint32_t)(kx*80);

        #pragma unroll
        for (int ks = 0; ks < 2; ks++){
            uint32_t ah[2][4], al[2][4];
            #pragma unroll
            for (int mi = 0; mi < 2; mi++){
                ldsm4(ah[mi], Ab       + ao + mi*1280 + ks*32);
                ldsm4(al[mi], Ab + APL + ao + mi*1280 + ks*32);
            }
            #pragma unroll
            for (int nj = 0; nj < NI/2; nj++){
                uint32_t bh[4], bl[4];
                ldsm4(bh, Bb       + boff + nj*1280 + ks*32);
                ldsm4(bl, Bb + BPL + boff + nj*1280 + ks*32);
                #pragma unroll
                for (int mi = 0; mi < 2; mi++){
                    mma16816(acc[mi][2*nj],   ah[mi], bh[0], bh[2]);
                    mma16816(acc[mi][2*nj],   ah[mi], bl[0], bl[2]);
                    mma16816(acc[mi][2*nj],   al[mi], bh[0], bh[2]);
                    mma16816(acc[mi][2*nj+1], ah[mi], bh[1], bh[3]);
                    mma16816(acc[mi][2*nj+1], ah[mi], bl[1], bl[3]);
                    mma16816(acc[mi][2*nj+1], al[mi], bh[1], bh[3]);
                }
            }
        }
    }
#undef ALOAD
#undef BLOAD

    float* base = out + ((size_t)(b*K_H + h)*K_W)*Cout;
    #pragma unroll
    for (int mi = 0; mi < 2; mi++){
        int px = wm*32 + mi*16 + (lane >> 2);
        #pragma unroll
        for (int ni = 0; ni < NI; ni++){
            int co = cob + wn*(BN/2) + ni*8 + (lane & 3)*2;
            float bv0 = __ldg(bias + co), bv1 = __ldg(bias + co + 1);
            float2 v0 = make_float2(acc[mi][ni][0] + bv0, acc[mi][ni][1] + bv1);
            float2 v1 = make_float2(acc[mi][ni][2] + bv0, acc[mi][ni][3] + bv1);
            *(float2*)(base + (size_t)px*Cout + co)     = v0;
            *(float2*)(base + (size_t)(px+8)*Cout + co) = v1;
        }
    }
}

// ======================= GroupNorm =======================
template<int LAYER>
__global__ void gn_stats(){
    constexpr int C  = (LAYER==1)?256:(LAYER==2)?128:64;
    constexpr int Cg = (LAYER==3)?16:32;
    constexpr int G  = C/Cg;
    const float* y = (LAYER==1)?g_y1:(LAYER==2)?g_y2:g_y3;
    int bh = blockIdx.x;
    int b = bh >> 7;
    __shared__ float ss[8], sq[8];
    int tid = threadIdx.x;
    if (tid < G){ ss[tid] = 0.f; sq[tid] = 0.f; }
    __syncthreads();
    for (int c = tid; c < C; c += 256){
        float s = 0.f, q = 0.f;
        const float* p = y + (size_t)bh*K_W*C + c;
        #pragma unroll 4
        for (int px = 0; px < K_W; px++){
            float v = p[(size_t)px*C];
            s += v; q = fmaf(v, v, q);
        }
        atomicAdd(&ss[c/Cg], s);
        atomicAdd(&sq[c/Cg], q);
    }
    __syncthreads();
    if (tid < G){
        atomicAdd(&g_gs[LAYER-1][b*G + tid], ss[tid]);
        atomicAdd(&g_gq[LAYER-1][b*G + tid], sq[tid]);
    }
}

template<int LAYER>
__global__ void gn_fin(const float* __restrict__ gamma, const float* __restrict__ beta){
    constexpr int C  = (LAYER==1)?256:(LAYER==2)?128:64;
    constexpr int Cg = (LAYER==3)?16:32;
    float* sct = (LAYER==1)?g_sct1:(LAYER==2)?g_sct2:g_sct3;
    int i = blockIdx.x*blockDim.x + threadIdx.x;
    if (i >= K_B*C) return;
    int b = i / C, c = i % C;
    int g = b*(C/Cg) + c/Cg;
    float n   = (float)Cg * (float)K_HW;
    float mu  = g_gs[LAYER-1][g] / n;
    float var = g_gq[LAYER-1][g] / n - mu*mu;
    float inv = rsqrtf(var + 1e-5f);
    float s = gamma[c]*inv;
    sct[2*i]   = s;
    sct[2*i+1] = beta[c] - mu*s;
}

// ======================= segment pooling (GN3+relu fused) =======================
__global__ void pool_seg(const int* __restrict__ masks){
    __shared__ float sacc[K_NS][64];
    __shared__ float scnt[K_NS];
    int bh = blockIdx.x;
    int b = bh >> 7;
    int tid = threadIdx.x;
    for (int i = tid; i < K_NS*64; i += 256) (&sacc[0][0])[i] = 0.f;
    if (tid < K_NS) scnt[tid] = 0.f;
    __syncthreads();

    int c = tid & 63, g = tid >> 6;
    float2 st = ((const float2*)g_sct3)[b*64 + c];
    const float* yb = g_y3 + (size_t)bh*K_W*64;
    const int* mrow = masks + (size_t)bh*K_W;
    for (int px = g; px < K_W; px += 4){
        int seg = mrow[px];
        float v = fmaxf(fmaf(st.x, yb[(size_t)px*64 + c], st.y), 0.f);
        atomicAdd(&sacc[seg][c], v);
        if (c == 0) atomicAdd(&scnt[seg], 1.f);
    }
    __syncthreads();
    for (int i = tid; i < K_NS*64; i += 256) atomicAdd(&g_psum[b*K_NS*64 + i], (&sacc[0][0])[i]);
    if (tid < K_NS) atomicAdd(&g_pcnt[b*K_NS + tid], scnt[tid]);
}

// ======================= heads =======================
__global__ void heads(const float* __restrict__ wbox, const float* __restrict__ bbox,
                      const float* __restrict__ wconf, const float* __restrict__ bconf,
                      float* __restrict__ outp){
    int t = threadIdx.x;
    if (t >= K_B*32) return;
    int b = t / 32, o = t % 32, s = o + 1;
    float inv = 1.f / fmaxf(g_pcnt[b*K_NS + s], 1e-4f);
    const float* ps = &g_psum[(b*K_NS + s)*64];
    float pooled[64];
    #pragma unroll
    for (int c = 0; c < 64; c++) pooled[c] = ps[c]*inv;
    #pragma unroll
    for (int k = 0; k < 7; k++){
        float d = bbox[k];
        #pragma unroll
        for (int c = 0; c < 64; c++) d = fmaf(pooled[c], wbox[k*64+c], d);
        outp[(b*32 + o)*7 + k] = d;
    }
    float d = bconf[0];
    #pragma unroll
    for (int c = 0; c < 64; c++) d = fmaf(pooled[c], wconf[c], d);
    outp[K_B*32*7 + b*32 + o] = d;
}

// ======================= launch =======================
extern "C" void kernel_launch(void* const* d_in, const int* in_sizes, int n_in,
                              void* d_out, int out_size){
    const float* x      = (const float*)d_in[0];
    const int*   masks  = (const int*)  d_in[1];
    const float* wcoord = (const float*)d_in[2];
    const float* bcoord = (const float*)d_in[3];
    const float* w1     = (const float*)d_in[4];
    const float* b1     = (const float*)d_in[5];
    const float* gm1    = (const float*)d_in[6];
    const float* bt1    = (const float*)d_in[7];
    const float* w2     = (const float*)d_in[8];
    const float* b2     = (const float*)d_in[9];
    const float* gm2    = (const float*)d_in[10];
    const float* bt2    = (const float*)d_in[11];
    const float* w3     = (const float*)d_in[12];
    const float* b3     = (const float*)d_in[13];
    const float* gm3    = (const float*)d_in[14];
    const float* bt3    = (const float*)d_in[15];
    const float* wbox   = (const float*)d_in[16];
    const float* bbox   = (const float*)d_in[17];
    const float* wconf  = (const float*)d_in[18];
    const float* bconf  = (const float*)d_in[19];
    float* outp = (float*)d_out;

    const int SM1 = 4*10496 + 6*128*80;   // 103424
    const int SM2 = SM1;
    const int SM3 = 4*10496 + 6*64*80;    // 72704
    cudaFuncSetAttribute(conv_hmma<1>, cudaFuncAttributeMaxDynamicSharedMemorySize, SM1);
    cudaFuncSetAttribute(conv_hmma<2>, cudaFuncAttributeMaxDynamicSharedMemorySize, SM2);
    cudaFuncSetAttribute(conv_hmma<3>, cudaFuncAttributeMaxDynamicSharedMemorySize, SM3);

    // Launch order chosen so conv_hmma<1> lands in the ncu-captured slot (4th kernel).
    repack_w<1><<<512,256>>>(w1);
    { dim3 g(9, K_H, K_B); xform1<<<g,256>>>(x, wcoord, bcoord); }
    zero_bufs<<<33,256>>>();
    { dim3 g(K_H, K_B, 2); conv_hmma<1><<<g,256,SM1>>>(b1); }   // <- profiled
    repack_w<2><<<256,256>>>(w2);
    repack_w<3><<<128,256>>>(w3);
    gn_stats<1><<<K_B*K_H,256>>>();
    gn_fin<1><<<(K_B*256+255)/256,256>>>(gm1, bt1);
    act_xform<2><<<(int)(((size_t)K_B*K_HW*256)/256),256>>>();

    { dim3 g(K_H, K_B, 1); conv_hmma<2><<<g,256,SM2>>>(b2); }
    gn_stats<2><<<K_B*K_H,256>>>();
    gn_fin<2><<<(K_B*128+255)/256,256>>>(gm2, bt2);
    act_xform<3><<<(int)(((size_t)K_B*K_HW*128)/256),256>>>();

    { dim3 g(K_H, K_B, 1); conv_hmma<3><<<g,256,SM3>>>(b3); }
    gn_stats<3><<<K_B*K_H,256>>>();
    gn_fin<3><<<1,256>>>(gm3, bt3);

    pool_seg<<<K_B*K_H,256>>>(masks);
    heads<<<1,128>>>(wbox, bbox, wconf, bconf, outp);
}

// round 6
// speedup vs baseline: 1.3826x; 1.3826x over previous
#include <cuda_runtime.h>
#include <cuda_fp16.h>
#include <cstdint>

#define K_H  128
#define K_W  128
#define K_HW 16384
#define K_B  4
#define K_NS 33

// ======================= device scratch (static, no alloc) =======================
// activations: fp16 hi / lo planes, NHWC
__device__ __align__(16) __half g_a1h[(size_t)K_B*K_HW*576];
__device__ __align__(16) __half g_a1l[(size_t)K_B*K_HW*576];
__device__ __align__(16) __half g_a2h[(size_t)K_B*K_HW*256];
__device__ __align__(16) __half g_a2l[(size_t)K_B*K_HW*256];
__device__ __align__(16) __half g_a3h[(size_t)K_B*K_HW*128];
__device__ __align__(16) __half g_a3l[(size_t)K_B*K_HW*128];
__device__ __align__(16) float g_y1[(size_t)K_B*K_HW*256];
__device__ __align__(16) float g_y2[(size_t)K_B*K_HW*128];
__device__ __align__(16) float g_y3[(size_t)K_B*K_HW*64];
// weights [k][co][ci] fp16 (single plane)
__device__ __align__(16) __half g_w1[9*256*576];
__device__ __align__(16) __half g_w2[9*128*256];
__device__ __align__(16) __half g_w3[9*64*128];
__device__ float g_gs[3][64], g_gq[3][64];
__device__ float g_sct1[K_B*256*2], g_sct2[K_B*128*2], g_sct3[K_B*64*2];
__device__ float g_psum[K_B*K_NS*64];
__device__ float g_pcnt[K_B*K_NS];

// ======================= helpers =======================
__device__ __forceinline__ uint32_t smem_u32(const void* p) {
    uint32_t a;
    asm("{ .reg .u64 t; cvta.to.shared.u64 t, %1; cvt.u32.u64 %0, t; }" : "=r"(a) : "l"(p));
    return a;
}
__device__ __forceinline__ void cp16(uint32_t dst, const void* src, uint32_t sz){
    asm volatile("cp.async.cg.shared.global [%0], [%1], 16, %2;" :: "r"(dst), "l"(src), "r"(sz));
}
#define CP_COMMIT() asm volatile("cp.async.commit_group;" ::: "memory")
#define CP_WAIT1()  asm volatile("cp.async.wait_group 1;"  ::: "memory")
__device__ __forceinline__ void ldsm4(uint32_t (&r)[4], uint32_t a){
    asm volatile("ldmatrix.sync.aligned.m8n8.x4.shared.b16 {%0,%1,%2,%3}, [%4];"
        : "=r"(r[0]), "=r"(r[1]), "=r"(r[2]), "=r"(r[3]) : "r"(a));
}
__device__ __forceinline__ void mma16816(float (&d)[4], const uint32_t (&a)[4],
                                         uint32_t b0, uint32_t b1){
    asm volatile(
        "mma.sync.aligned.m16n8k16.row.col.f32.f16.f16.f32 "
        "{%0,%1,%2,%3},{%4,%5,%6,%7},{%8,%9},{%0,%1,%2,%3};"
        : "+f"(d[0]), "+f"(d[1]), "+f"(d[2]), "+f"(d[3])
        : "r"(a[0]), "r"(a[1]), "r"(a[2]), "r"(a[3]), "r"(b0), "r"(b1));
}
__device__ __forceinline__ void split_hl(float v, __half& h, __half& l){
    h = __float2half_rn(v);
    l = __float2half_rn(v - __half2float(h));
}

// ======================= small kernels =======================
__global__ void zero_bufs(){
    int i = blockIdx.x*256 + threadIdx.x;
    if (i < K_B*K_NS*64) g_psum[i] = 0.f;
    if (i < K_B*K_NS)    g_pcnt[i] = 0.f;
    if (i < 64){
        g_gs[0][i]=0.f; g_gs[1][i]=0.f; g_gs[2][i]=0.f;
        g_gq[0][i]=0.f; g_gq[1][i]=0.f; g_gq[2][i]=0.f;
    }
}

template<int LAYER>
__global__ void repack_w(const float* __restrict__ w){
    constexpr int Cin  = (LAYER==1)?576:(LAYER==2)?256:128;
    constexpr int Cout = (LAYER==1)?256:(LAYER==2)?128:64;
    __half* wp = (LAYER==1)?g_w1:(LAYER==2)?g_w2:g_w3;
    int n = Cout*Cin*9;
    for (int i = blockIdx.x*blockDim.x + threadIdx.x; i < n; i += gridDim.x*blockDim.x){
        int k  = i % 9;
        int t  = i / 9;
        int ci = t % Cin;
        int co = t / Cin;
        wp[((size_t)k*Cout + co)*Cin + ci] = __float2half_rn(w[i]);
    }
}

__global__ void xform1(const float* __restrict__ x, const float* __restrict__ wc,
                       const float* __restrict__ bc){
    __shared__ float tile[64][129];
    int cblk = blockIdx.x, h = blockIdx.y, b = blockIdx.z, tid = threadIdx.x;
    if (cblk < 8){
        for (int i = tid; i < 64*128; i += 256){
            int ci = i >> 7, w = i & 127;
            tile[ci][w] = x[(((size_t)b*512 + cblk*64 + ci)*K_H + h)*K_W + w];
        }
    } else {
        for (int i = tid; i < 64*128; i += 256){
            int ci = i >> 7, w = i & 127;
            tile[ci][w] = fmaxf(wc[2*ci]*(float)w + wc[2*ci+1]*(float)h + bc[ci], 0.f);
        }
    }
    __syncthreads();
    for (int i = tid; i < 64*128; i += 256){
        int px = i >> 6, c = i & 63;
        __half hv, lv;
        split_hl(tile[c][px], hv, lv);
        size_t o = (((size_t)b*K_H + h)*K_W + px)*576 + cblk*64 + c;
        g_a1h[o] = hv; g_a1l[o] = lv;
    }
}

template<int L>
__global__ void act_xform(){
    constexpr int C = (L==2)?256:128;
    const float* __restrict__ y   = (L==2)?g_y1:g_y2;
    const float* __restrict__ sct = (L==2)?g_sct1:g_sct2;
    __half* __restrict__ ah = (L==2)?g_a2h:g_a3h;
    __half* __restrict__ al = (L==2)?g_a2l:g_a3l;
    size_t idx = (size_t)blockIdx.x*256 + threadIdx.x;
    if (idx >= (size_t)K_B*K_HW*C) return;
    int c = (int)(idx % C);
    int b = (int)(idx / ((size_t)K_HW*C));
    float2 st = ((const float2*)sct)[b*C + c];
    float v = fmaxf(fmaf(st.x, y[idx], st.y), 0.f);
    __half hv, lv;
    split_hl(v, hv, lv);
    ah[idx] = hv; al[idx] = lv;
}

// ======================= conv3x3 via mma.sync fp16x2 (A split), group pipeline =======================
// group g = (ky, ci-chunk); per group: A tile (2 planes, 130 rows w/ guards) + 3 B slots (kx).
// 2-buffer group pipeline, 2 syncs/group, GN stats fused in epilogue.
template<int LAYER>
__global__ void __launch_bounds__(256,2)
conv_hmma(const float* __restrict__ bias){
    constexpr int Cin  = (LAYER==1)?576:(LAYER==2)?256:128;
    constexpr int Cout = (LAYER==1)?256:(LAYER==2)?128:64;
    constexpr int Cg   = (LAYER==3)?16:32;
    constexpr int BN   = (Cout>=128)?128:64;
    constexpr int NCB  = Cin/32;
    constexpr int NG   = 3*NCB;          // groups (ky, cb)
    constexpr int NI   = BN/16;
    constexpr int BIT  = BN/64;          // cp16 per thread per B slot
    constexpr int APL  = 10496;          // A plane bytes (130 rows * 80, padded)
    constexpr int BPL  = BN*80;          // B slot bytes
    constexpr int ABYT = 4*APL;          // 2 bufs * 2 planes

    const __half* __restrict__ act_h = (LAYER==1)?g_a1h:(LAYER==2)?g_a2h:g_a3h;
    const __half* __restrict__ act_l = (LAYER==1)?g_a1l:(LAYER==2)?g_a2l:g_a3l;
    const __half* __restrict__ w_p   = (LAYER==1)?g_w1:(LAYER==2)?g_w2:g_w3;
    float* __restrict__ out = (LAYER==1)?g_y1:(LAYER==2)?g_y2:g_y3;

    extern __shared__ __align__(128) char dsm[];
    const uint32_t sbase = smem_u32(dsm);

    const int tid  = threadIdx.x;
    const int lane = tid & 31;
    const int wm   = (tid >> 5) & 3;
    const int wn   = tid >> 7;
    const int h    = blockIdx.x;
    const int b    = blockIdx.y;
    const int cob  = blockIdx.z*BN;

    // zero guard rows (px=-1 -> row0, px=128 -> row129) in all 4 A planes
    if (tid < 160){
        int pl = tid/40, rem = tid%40;
        uint32_t row = (rem >= 20) ? 129u : 0u;
        *(uint32_t*)(dsm + pl*APL + row*80 + (rem%20)*4) = 0u;
    }

    float acc[2][NI][4];
    #pragma unroll
    for (int mi=0;mi<2;mi++)
        #pragma unroll
        for (int ni=0;ni<NI;ni++)
            #pragma unroll
            for (int j=0;j<4;j++) acc[mi][ni][j] = 0.f;

#define LOADG(G, BUF) { \
        const int g_ = (G); \
        const int ky_ = g_/NCB, cb_ = g_ - ky_*NCB; \
        const int hh_ = h + ky_ - 1; \
        const uint32_t sz_ = (hh_>=0 && hh_<K_H) ? 16u : 0u; \
        const int hc_ = hh_<0?0:(hh_>127?127:hh_); \
        const size_t so_ = ((size_t)(b*K_H + hc_)*K_W)*Cin + cb_*32; \
        const uint32_t ab_ = sbase + (uint32_t)(BUF)*2u*APL; \
        _Pragma("unroll") \
        for (int it = 0; it < 2; it++){ \
            int idx_ = it*256 + tid, r_ = idx_>>2, q_ = idx_&3; \
            uint32_t d_ = ab_ + (r_+1)*80 + q_*16; \
            const size_t off_ = so_ + (size_t)r_*Cin + q_*8; \
            cp16(d_,       act_h + off_, sz_); \
            cp16(d_ + APL, act_l + off_, sz_); \
        } \
        const uint32_t bb_ = sbase + ABYT + (uint32_t)(BUF)*3u*BPL; \
        _Pragma("unroll") \
        for (int kx_ = 0; kx_ < 3; kx_++){ \
            const size_t wo_ = ((size_t)((ky_*3 + kx_)*Cout + cob))*Cin + cb_*32; \
            _Pragma("unroll") \
            for (int it = 0; it < BIT; it++){ \
                int idx_ = it*256 + tid, r_ = idx_>>2, q_ = idx_&3; \
                cp16(bb_ + kx_*BPL + r_*80 + q_*16, w_p + wo_ + (size_t)r_*Cin + q_*8, 16u); \
            } \
        } }

    const uint32_t aoff0 = (uint32_t)((wm*32 + (lane & 15))*80 + (lane >> 4)*16);
    const uint32_t boff  = (uint32_t)((wn*(BN/2) + (lane & 15))*80 + (lane >> 4)*16);

    LOADG(0, 0); CP_COMMIT();
    LOADG(1, 1); CP_COMMIT();

    #pragma unroll 1
    for (int g = 0; g < NG; ++g){
        CP_WAIT1();          // group g resident
        __syncthreads();

        const uint32_t Ab  = sbase + (uint32_t)(g&1)*2u*APL;
        const uint32_t Bb0 = sbase + ABYT + (uint32_t)(g&1)*3u*BPL;

        #pragma unroll
        for (int kx = 0; kx < 3; kx++){
            const uint32_t Bb = Bb0 + kx*BPL;
            const uint32_t ao = aoff0 + kx*80;
            #pragma unroll
            for (int ks = 0; ks < 2; ks++){
                uint32_t ah[2][4], al[2][4];
                #pragma unroll
                for (int mi = 0; mi < 2; mi++){
                    ldsm4(ah[mi], Ab       + ao + mi*1280 + ks*32);
                    ldsm4(al[mi], Ab + APL + ao + mi*1280 + ks*32);
                }
                #pragma unroll
                for (int nj = 0; nj < NI/2; nj++){
                    uint32_t bh[4];
                    ldsm4(bh, Bb + boff + nj*1280 + ks*32);
                    #pragma unroll
                    for (int mi = 0; mi < 2; mi++){
                        mma16816(acc[mi][2*nj],   ah[mi], bh[0], bh[2]);
                        mma16816(acc[mi][2*nj],   al[mi], bh[0], bh[2]);
                        mma16816(acc[mi][2*nj+1], ah[mi], bh[1], bh[3]);
                        mma16816(acc[mi][2*nj+1], al[mi], bh[1], bh[3]);
                    }
                }
            }
        }

        __syncthreads();     // all warps done with buffer g&1
        if (g + 2 < NG) LOADG(g + 2, g&1);
        CP_COMMIT();
    }
#undef LOADG

    // epilogue: +bias -> fp32 NHWC, with fused GN partial stats
    float s0=0.f, q0=0.f, s1=0.f, q1=0.f;
    float* base = out + ((size_t)(b*K_H + h)*K_W)*Cout;
    #pragma unroll
    for (int mi = 0; mi < 2; mi++){
        int px = wm*32 + mi*16 + (lane >> 2);
        #pragma unroll
        for (int ni = 0; ni < NI; ni++){
            int co = cob + wn*(BN/2) + ni*8 + (lane & 3)*2;
            float bv0 = __ldg(bias + co), bv1 = __ldg(bias + co + 1);
            float v0 = acc[mi][ni][0] + bv0, v1 = acc[mi][ni][1] + bv1;
            float v2 = acc[mi][ni][2] + bv0, v3 = acc[mi][ni][3] + bv1;
            *(float2*)(base + (size_t)px*Cout + co)     = make_float2(v0, v1);
            *(float2*)(base + (size_t)(px+8)*Cout + co) = make_float2(v2, v3);
            if (ni < NI/2){
                s0 += (v0+v1)+(v2+v3);
                q0 += v0*v0 + v1*v1 + v2*v2 + v3*v3;
            } else {
                s1 += (v0+v1)+(v2+v3);
                q1 += v0*v0 + v1*v1 + v2*v2 + v3*v3;
            }
        }
    }
    #pragma unroll
    for (int o = 16; o; o >>= 1){
        s0 += __shfl_down_sync(0xffffffffu, s0, o);
        q0 += __shfl_down_sync(0xffffffffu, q0, o);
        s1 += __shfl_down_sync(0xffffffffu, s1, o);
        q1 += __shfl_down_sync(0xffffffffu, q1, o);
    }
    if (lane == 0){
        constexpr int G = Cout/Cg;
        int gbase = (cob + wn*(BN/2))/Cg;
        atomicAdd(&g_gs[LAYER-1][b*G + gbase],     s0);
        atomicAdd(&g_gq[LAYER-1][b*G + gbase],     q0);
        atomicAdd(&g_gs[LAYER-1][b*G + gbase + 1], s1);
        atomicAdd(&g_gq[LAYER-1][b*G + gbase + 1], q1);
    }
}

// ======================= GroupNorm finalize =======================
template<int LAYER>
__global__ void gn_fin(const float* __restrict__ gamma, const float* __restrict__ beta){
    constexpr int C  = (LAYER==1)?256:(LAYER==2)?128:64;
    constexpr int Cg = (LAYER==3)?16:32;
    float* sct = (LAYER==1)?g_sct1:(LAYER==2)?g_sct2:g_sct3;
    int i = blockIdx.x*blockDim.x + threadIdx.x;
    if (i >= K_B*C) return;
    int b = i / C, c = i % C;
    int g = b*(C/Cg) + c/Cg;
    float n   = (float)Cg * (float)K_HW;
    float mu  = g_gs[LAYER-1][g] / n;
    float var = g_gq[LAYER-1][g] / n - mu*mu;
    float inv = rsqrtf(var + 1e-5f);
    float s = gamma[c]*inv;
    sct[2*i]   = s;
    sct[2*i+1] = beta[c] - mu*s;
}

// ======================= segment pooling (GN3+relu fused) =======================
__global__ void pool_seg(const int* __restrict__ masks){
    __shared__ float sacc[K_NS][64];
    __shared__ float scnt[K_NS];
    int bh = blockIdx.x;
    int b = bh >> 7;
    int tid = threadIdx.x;
    for (int i = tid; i < K_NS*64; i += 256) (&sacc[0][0])[i] = 0.f;
    if (tid < K_NS) scnt[tid] = 0.f;
    __syncthreads();

    int c = tid & 63, g = tid >> 6;
    float2 st = ((const float2*)g_sct3)[b*64 + c];
    const float* yb = g_y3 + (size_t)bh*K_W*64;
    const int* mrow = masks + (size_t)bh*K_W;
    for (int px = g; px < K_W; px += 4){
        int seg = mrow[px];
        float v = fmaxf(fmaf(st.x, yb[(size_t)px*64 + c], st.y), 0.f);
        atomicAdd(&sacc[seg][c], v);
        if (c == 0) atomicAdd(&scnt[seg], 1.f);
    }
    __syncthreads();
    for (int i = tid; i < K_NS*64; i += 256) atomicAdd(&g_psum[b*K_NS*64 + i], (&sacc[0][0])[i]);
    if (tid < K_NS) atomicAdd(&g_pcnt[b*K_NS + tid], scnt[tid]);
}

// ======================= heads =======================
__global__ void heads(const float* __restrict__ wbox, const float* __restrict__ bbox,
                      const float* __restrict__ wconf, const float* __restrict__ bconf,
                      float* __restrict__ outp){
    int t = threadIdx.x;
    if (t >= K_B*32) return;
    int b = t / 32, o = t % 32, s = o + 1;
    float inv = 1.f / fmaxf(g_pcnt[b*K_NS + s], 1e-4f);
    const float* ps = &g_psum[(b*K_NS + s)*64];
    float pooled[64];
    #pragma unroll
    for (int c = 0; c < 64; c++) pooled[c] = ps[c]*inv;
    #pragma unroll
    for (int k = 0; k < 7; k++){
        float d = bbox[k];
        #pragma unroll
        for (int c = 0; c < 64; c++) d = fmaf(pooled[c], wbox[k*64+c], d);
        outp[(b*32 + o)*7 + k] = d;
    }
    float d = bconf[0];
    #pragma unroll
    for (int c = 0; c < 64; c++) d = fmaf(pooled[c], wconf[c], d);
    outp[K_B*32*7 + b*32 + o] = d;
}

// ======================= launch =======================
extern "C" void kernel_launch(void* const* d_in, const int* in_sizes, int n_in,
                              void* d_out, int out_size){
    const float* x      = (const float*)d_in[0];
    const int*   masks  = (const int*)  d_in[1];
    const float* wcoord = (const float*)d_in[2];
    const float* bcoord = (const float*)d_in[3];
    const float* w1     = (const float*)d_in[4];
    const float* b1     = (const float*)d_in[5];
    const float* gm1    = (const float*)d_in[6];
    const float* bt1    = (const float*)d_in[7];
    const float* w2     = (const float*)d_in[8];
    const float* b2     = (const float*)d_in[9];
    const float* gm2    = (const float*)d_in[10];
    const float* bt2    = (const float*)d_in[11];
    const float* w3     = (const float*)d_in[12];
    const float* b3     = (const float*)d_in[13];
    const float* gm3    = (const float*)d_in[14];
    const float* bt3    = (const float*)d_in[15];
    const float* wbox   = (const float*)d_in[16];
    const float* bbox   = (const float*)d_in[17];
    const float* wconf  = (const float*)d_in[18];
    const float* bconf  = (const float*)d_in[19];
    float* outp = (float*)d_out;

    const int SM1 = 4*10496 + 6*128*80;   // 103424
    const int SM2 = SM1;
    const int SM3 = 4*10496 + 6*64*80;    // 72704
    cudaFuncSetAttribute(conv_hmma<1>, cudaFuncAttributeMaxDynamicSharedMemorySize, SM1);
    cudaFuncSetAttribute(conv_hmma<2>, cudaFuncAttributeMaxDynamicSharedMemorySize, SM2);
    cudaFuncSetAttribute(conv_hmma<3>, cudaFuncAttributeMaxDynamicSharedMemorySize, SM3);

    // conv_hmma<1> kept in the 4th launch slot for ncu capture.
    repack_w<1><<<512,256>>>(w1);
    { dim3 g(9, K_H, K_B); xform1<<<g,256>>>(x, wcoord, bcoord); }
    zero_bufs<<<33,256>>>();
    { dim3 g(K_H, K_B, 2); conv_hmma<1><<<g,256,SM1>>>(b1); }   // <- profiled
    repack_w<2><<<256,256>>>(w2);
    repack_w<3><<<128,256>>>(w3);
    gn_fin<1><<<(K_B*256+255)/256,256>>>(gm1, bt1);
    act_xform<2><<<(int)(((size_t)K_B*K_HW*256)/256),256>>>();

    { dim3 g(K_H, K_B, 1); conv_hmma<2><<<g,256,SM2>>>(b2); }
    gn_fin<2><<<(K_B*128+255)/256,256>>>(gm2, bt2);
    act_xform<3><<<(int)(((size_t)K_B*K_HW*128)/256),256>>>();

    { dim3 g(K_H, K_B, 1); conv_hmma<3><<<g,256,SM3>>>(b3); }
    gn_fin<3><<<1,256>>>(gm3, bt3);

    pool_seg<<<K_B*K_H,256>>>(masks);
    heads<<<1,128>>>(wbox, bbox, wconf, bconf, outp);
}

// round 7
// speedup vs baseline: 1.4742x; 1.0663x over previous
#include <cuda_runtime.h>
#include <cuda_fp16.h>
#include <cstdint>

#define K_H  128
#define K_W  128
#define K_HW 16384
#define K_B  4
#define K_NS 33

// ======================= device scratch (static, no alloc) =======================
// activations: fp16 hi / lo planes, NHWC, padded by ONE image row each side
__device__ __align__(16) __half g_a1h[(size_t)(K_B*K_HW + 2*K_W)*576];
__device__ __align__(16) __half g_a1l[(size_t)(K_B*K_HW + 2*K_W)*576];
__device__ __align__(16) __half g_a2h[(size_t)(K_B*K_HW + 2*K_W)*256];
__device__ __align__(16) __half g_a2l[(size_t)(K_B*K_HW + 2*K_W)*256];
__device__ __align__(16) __half g_a3h[(size_t)(K_B*K_HW + 2*K_W)*128];
__device__ __align__(16) __half g_a3l[(size_t)(K_B*K_HW + 2*K_W)*128];
__device__ __align__(16) float g_y1[(size_t)K_B*K_HW*256];
__device__ __align__(16) float g_y2[(size_t)K_B*K_HW*128];
__device__ __align__(16) float g_y3[(size_t)K_B*K_HW*64];
__device__ __align__(16) __half g_w1[9*256*576];
__device__ __align__(16) __half g_w2[9*128*256];
__device__ __align__(16) __half g_w3[9*64*128];
__device__ float g_gs[3][64], g_gq[3][64];
__device__ float g_sct1[K_B*256*2], g_sct2[K_B*128*2], g_sct3[K_B*64*2];
__device__ float g_psum[K_B*K_NS*64];
__device__ float g_pcnt[K_B*K_NS];

// ======================= helpers =======================
__device__ __forceinline__ uint32_t smem_u32(const void* p) {
    uint32_t a;
    asm("{ .reg .u64 t; cvta.to.shared.u64 t, %1; cvt.u32.u64 %0, t; }" : "=r"(a) : "l"(p));
    return a;
}
__device__ __forceinline__ void cp16(uint32_t dst, const void* src, uint32_t sz){
    asm volatile("cp.async.cg.shared.global [%0], [%1], 16, %2;" :: "r"(dst), "l"(src), "r"(sz));
}
#define CP_COMMIT() asm volatile("cp.async.commit_group;" ::: "memory")
#define CP_WAIT0()  asm volatile("cp.async.wait_group 0;"  ::: "memory")
__device__ __forceinline__ void ldsm4(uint32_t (&r)[4], uint32_t a){
    asm volatile("ldmatrix.sync.aligned.m8n8.x4.shared.b16 {%0,%1,%2,%3}, [%4];"
        : "=r"(r[0]), "=r"(r[1]), "=r"(r[2]), "=r"(r[3]) : "r"(a));
}
__device__ __forceinline__ void mma16816(float (&d)[4], const uint32_t (&a)[4],
                                         uint32_t b0, uint32_t b1){
    asm volatile(
        "mma.sync.aligned.m16n8k16.row.col.f32.f16.f16.f32 "
        "{%0,%1,%2,%3},{%4,%5,%6,%7},{%8,%9},{%0,%1,%2,%3};"
        : "+f"(d[0]), "+f"(d[1]), "+f"(d[2]), "+f"(d[3])
        : "r"(a[0]), "r"(a[1]), "r"(a[2]), "r"(a[3]), "r"(b0), "r"(b1));
}
__device__ __forceinline__ void split_hl(float v, __half& h, __half& l){
    h = __float2half_rn(v);
    l = __float2half_rn(v - __half2float(h));
}

// ======================= small kernels =======================
__global__ void zero_bufs(){
    int i = blockIdx.x*256 + threadIdx.x;
    if (i < K_B*K_NS*64) g_psum[i] = 0.f;
    if (i < K_B*K_NS)    g_pcnt[i] = 0.f;
    if (i < 64){
        g_gs[0][i]=0.f; g_gs[1][i]=0.f; g_gs[2][i]=0.f;
        g_gq[0][i]=0.f; g_gq[1][i]=0.f; g_gq[2][i]=0.f;
    }
}

template<int LAYER>
__global__ void repack_w(const float* __restrict__ w){
    constexpr int Cin  = (LAYER==1)?576:(LAYER==2)?256:128;
    constexpr int Cout = (LAYER==1)?256:(LAYER==2)?128:64;
    __half* wp = (LAYER==1)?g_w1:(LAYER==2)?g_w2:g_w3;
    int n = Cout*Cin*9;
    for (int i = blockIdx.x*blockDim.x + threadIdx.x; i < n; i += gridDim.x*blockDim.x){
        int k  = i % 9;
        int t  = i / 9;
        int ci = t % Cin;
        int co = t / Cin;
        wp[((size_t)k*Cout + co)*Cin + ci] = __float2half_rn(w[i]);
    }
}

__global__ void xform1(const float* __restrict__ x, const float* __restrict__ wc,
                       const float* __restrict__ bc){
    __shared__ float tile[64][129];
    int cblk = blockIdx.x, h = blockIdx.y, b = blockIdx.z, tid = threadIdx.x;
    if (cblk < 8){
        for (int i = tid; i < 64*128; i += 256){
            int ci = i >> 7, w = i & 127;
            tile[ci][w] = x[(((size_t)b*512 + cblk*64 + ci)*K_H + h)*K_W + w];
        }
    } else {
        for (int i = tid; i < 64*128; i += 256){
            int ci = i >> 7, w = i & 127;
            tile[ci][w] = fmaxf(wc[2*ci]*(float)w + wc[2*ci+1]*(float)h + bc[ci], 0.f);
        }
    }
    __syncthreads();
    for (int i = tid; i < 64*128; i += 256){
        int px = i >> 6, c = i & 63;
        __half hv, lv;
        split_hl(tile[c][px], hv, lv);
        size_t o = (size_t)(K_W)*576 + (((size_t)b*K_H + h)*K_W + px)*576 + cblk*64 + c;
        g_a1h[o] = hv; g_a1l[o] = lv;
    }
}

template<int L>
__global__ void act_xform(){
    constexpr int C = (L==2)?256:128;
    const float* __restrict__ y   = (L==2)?g_y1:g_y2;
    const float* __restrict__ sct = (L==2)?g_sct1:g_sct2;
    __half* __restrict__ ah = ((L==2)?g_a2h:g_a3h) + (size_t)K_W*C;
    __half* __restrict__ al = ((L==2)?g_a2l:g_a3l) + (size_t)K_W*C;
    size_t i4 = ((size_t)blockIdx.x*256 + threadIdx.x)*4;
    if (i4 >= (size_t)K_B*K_HW*C) return;
    int c = (int)(i4 % C);
    int b = (int)(i4 / ((size_t)K_HW*C));
    float4 v4 = *(const float4*)(y + i4);
    const float4 st01 = *(const float4*)(sct + (b*C + c)*2);
    const float4 st23 = *(const float4*)(sct + (b*C + c)*2 + 4);
    float v[4];
    v[0] = fmaxf(fmaf(st01.x, v4.x, st01.y), 0.f);
    v[1] = fmaxf(fmaf(st01.z, v4.y, st01.w), 0.f);
    v[2] = fmaxf(fmaf(st23.x, v4.z, st23.y), 0.f);
    v[3] = fmaxf(fmaf(st23.z, v4.w, st23.w), 0.f);
    __half hh[4], ll[4];
    #pragma unroll
    for (int j = 0; j < 4; j++) split_hl(v[j], hh[j], ll[j]);
    *(uint64_t*)(ah + i4) = *(uint64_t*)hh;
    *(uint64_t*)(al + i4) = *(uint64_t*)ll;
}

// ======================= conv3x3: fp16x2 mma.sync, 1 barrier/group, SR addressing =======================
template<int LAYER>
__global__ void __launch_bounds__(256,2)
conv_hmma(const float* __restrict__ bias){
    constexpr int Cin  = (LAYER==1)?576:(LAYER==2)?256:128;
    constexpr int Cout = (LAYER==1)?256:(LAYER==2)?128:64;
    constexpr int Cg   = (LAYER==3)?16:32;
    constexpr int BN   = (Cout>=128)?128:64;
    constexpr int NCB  = Cin/32;
    constexpr int NG   = 3*NCB;
    constexpr int NI   = BN/16;
    constexpr int BIT  = BN/64;
    constexpr int APL  = 10496;
    constexpr int BPL  = BN*80;
    constexpr int ABYT = 4*APL;
    constexpr int WK   = Cout*Cin;              // kx stride in W (elements)
    constexpr int A_KYADJ = K_W*Cin - (NCB-1)*32;
    constexpr int W_KYADJ = 3*Cout*Cin - (NCB-1)*32;

    const __half* __restrict__ act_h = ((LAYER==1)?g_a1h:(LAYER==2)?g_a2h:g_a3h) + (size_t)K_W*Cin;
    const __half* __restrict__ act_l = ((LAYER==1)?g_a1l:(LAYER==2)?g_a2l:g_a3l) + (size_t)K_W*Cin;
    const __half* __restrict__ w_p   = (LAYER==1)?g_w1:(LAYER==2)?g_w2:g_w3;
    float* __restrict__ out = (LAYER==1)?g_y1:(LAYER==2)?g_y2:g_y3;

    extern __shared__ __align__(128) char dsm[];
    const uint32_t sbase = smem_u32(dsm);

    const int tid  = threadIdx.x;
    const int lane = tid & 31;
    const int wm   = (tid >> 5) & 3;
    const int wn   = tid >> 7;
    const int h    = blockIdx.x;
    const int b    = blockIdx.y;
    const int cob  = blockIdx.z*BN;

    // zero guard rows (px=-1 -> row0, px=128 -> row129) in all 4 A planes
    if (tid < 160){
        int pl = tid/40, rem = tid%40;
        uint32_t row = (rem >= 20) ? 129u : 0u;
        *(uint32_t*)(dsm + pl*APL + row*80 + (rem%20)*4) = 0u;
    }

    float acc[2][NI][4];
    #pragma unroll
    for (int mi=0;mi<2;mi++)
        #pragma unroll
        for (int ni=0;ni<NI;ni++)
            #pragma unroll
            for (int j=0;j<4;j++) acc[mi][ni][j] = 0.f;

    // ---- thread-constant offsets ----
    uint32_t dA[2], dB[BIT];
    int atoff[2], wtoff[BIT];
    #pragma unroll
    for (int it = 0; it < 2; it++){
        int idx = it*256 + tid, r = idx >> 2, q = idx & 3;
        dA[it]    = sbase + (r+1)*80 + q*16;
        atoff[it] = r*Cin + q*8;
    }
    #pragma unroll
    for (int it = 0; it < BIT; it++){
        int idx = it*256 + tid, r = idx >> 2, q = idx & 3;
        dB[it]    = sbase + ABYT + r*80 + q*16;
        wtoff[it] = r*Cin + q*8;
    }

    // ---- load-side running state (points at group to LOAD next) ----
    const __half* pAh = act_h + ((size_t)(b*K_H + h) - 1)*K_W*Cin;
    const __half* pAl = act_l + ((size_t)(b*K_H + h) - 1)*K_W*Cin;
    const __half* pW  = w_p + (size_t)cob*Cin;
    int cbL = 0, kyL = 0;
    const uint32_t vmask = ((h > 0) ? 1u : 0u) | 2u | ((h < K_H-1) ? 4u : 0u);
    uint32_t szA = (vmask & 1u) ? 16u : 0u;

#define ISSUE_LOAD(POFF_A, POFF_B) { \
        _Pragma("unroll") \
        for (int it = 0; it < 2; it++){ \
            cp16(dA[it] + (POFF_A),       pAh + atoff[it], szA); \
            cp16(dA[it] + (POFF_A) + APL, pAl + atoff[it], szA); \
        } \
        _Pragma("unroll") \
        for (int kx = 0; kx < 3; kx++){ \
            _Pragma("unroll") \
            for (int it = 0; it < BIT; it++) \
                cp16(dB[it] + (POFF_B) + kx*BPL, pW + kx*WK + wtoff[it], 16u); \
        } \
        if (++cbL < NCB){ pAh += 32; pAl += 32; pW += 32; } \
        else { cbL = 0; ++kyL; pAh += A_KYADJ; pAl += A_KYADJ; pW += W_KYADJ; \
               szA = ((vmask >> kyL) & 1u) ? 16u : 0u; } }

    const uint32_t aoff0 = (uint32_t)((wm*32 + (lane & 15))*80 + (lane >> 4)*16);
    const uint32_t boff  = (uint32_t)((wn*(BN/2) + (lane & 15))*80 + (lane >> 4)*16);

    uint32_t poffA = 0, poffB = 0;            // compute-side parity offsets
    ISSUE_LOAD(0, 0); CP_COMMIT();            // group 0 -> buffer 0

    #pragma unroll 1
    for (int g = 0; g < NG; ++g){
        CP_WAIT0();
        __syncthreads();

        // issue loads for group g+1 into the other buffer
        if (g + 1 < NG) ISSUE_LOAD(2*APL - poffA, 3*BPL - poffB);
        CP_COMMIT();

        const uint32_t Ab  = sbase + poffA;
        const uint32_t Bb0 = sbase + ABYT + poffB;
        poffA ^= 2*APL; poffB ^= 3*BPL;

        #pragma unroll
        for (int kx = 0; kx < 3; kx++){
            const uint32_t Bb = Bb0 + kx*BPL;
            const uint32_t ao = aoff0 + kx*80;
            #pragma unroll
            for (int ks = 0; ks < 2; ks++){
                uint32_t ah[2][4], al[2][4];
                #pragma unroll
                for (int mi = 0; mi < 2; mi++){
                    ldsm4(ah[mi], Ab       + ao + mi*1280 + ks*32);
                    ldsm4(al[mi], Ab + APL + ao + mi*1280 + ks*32);
                }
                #pragma unroll
                for (int nj = 0; nj < NI/2; nj++){
                    uint32_t bh[4];
                    ldsm4(bh, Bb + boff + nj*1280 + ks*32);
                    #pragma unroll
                    for (int mi = 0; mi < 2; mi++){
                        mma16816(acc[mi][2*nj],   ah[mi], bh[0], bh[2]);
                        mma16816(acc[mi][2*nj],   al[mi], bh[0], bh[2]);
                        mma16816(acc[mi][2*nj+1], ah[mi], bh[1], bh[3]);
                        mma16816(acc[mi][2*nj+1], al[mi], bh[1], bh[3]);
                    }
                }
            }
        }
    }
#undef ISSUE_LOAD

    // epilogue: +bias -> fp32 NHWC, fused GN partial stats
    float s0=0.f, q0=0.f, s1=0.f, q1=0.f;
    float* base = out + ((size_t)(b*K_H + h)*K_W)*Cout;
    #pragma unroll
    for (int mi = 0; mi < 2; mi++){
        int px = wm*32 + mi*16 + (lane >> 2);
        #pragma unroll
        for (int ni = 0; ni < NI; ni++){
            int co = cob + wn*(BN/2) + ni*8 + (lane & 3)*2;
            float bv0 = __ldg(bias + co), bv1 = __ldg(bias + co + 1);
            float v0 = acc[mi][ni][0] + bv0, v1 = acc[mi][ni][1] + bv1;
            float v2 = acc[mi][ni][2] + bv0, v3 = acc[mi][ni][3] + bv1;
            *(float2*)(base + (size_t)px*Cout + co)     = make_float2(v0, v1);
            *(float2*)(base + (size_t)(px+8)*Cout + co) = make_float2(v2, v3);
            if (ni < NI/2){ s0 += (v0+v1)+(v2+v3); q0 += v0*v0+v1*v1+v2*v2+v3*v3; }
            else          { s1 += (v0+v1)+(v2+v3); q1 += v0*v0+v1*v1+v2*v2+v3*v3; }
        }
    }
    #pragma unroll
    for (int o = 16; o; o >>= 1){
        s0 += __shfl_down_sync(0xffffffffu, s0, o);
        q0 += __shfl_down_sync(0xffffffffu, q0, o);
        s1 += __shfl_down_sync(0xffffffffu, s1, o);
        q1 += __shfl_down_sync(0xffffffffu, q1, o);
    }
    if (lane == 0){
        constexpr int G = Cout/Cg;
        int gbase = (cob + wn*(BN/2))/Cg;
        atomicAdd(&g_gs[LAYER-1][b*G + gbase],     s0);
        atomicAdd(&g_gq[LAYER-1][b*G + gbase],     q0);
        atomicAdd(&g_gs[LAYER-1][b*G + gbase + 1], s1);
        atomicAdd(&g_gq[LAYER-1][b*G + gbase + 1], q1);
    }
}

// ======================= GroupNorm finalize =======================
template<int LAYER>
__global__ void gn_fin(const float* __restrict__ gamma, const float* __restrict__ beta){
    constexpr int C  = (LAYER==1)?256:(LAYER==2)?128:64;
    constexpr int Cg = (LAYER==3)?16:32;
    float* sct = (LAYER==1)?g_sct1:(LAYER==2)?g_sct2:g_sct3;
    int i = blockIdx.x*blockDim.x + threadIdx.x;
    if (i >= K_B*C) return;
    int b = i / C, c = i % C;
    int g = b*(C/Cg) + c/Cg;
    float n   = (float)Cg * (float)K_HW;
    float mu  = g_gs[LAYER-1][g] / n;
    float var = g_gq[LAYER-1][g] / n - mu*mu;
    float inv = rsqrtf(var + 1e-5f);
    float s = gamma[c]*inv;
    sct[2*i]   = s;
    sct[2*i+1] = beta[c] - mu*s;
}

// ======================= segment pooling (GN3+relu fused) =======================
__global__ void pool_seg(const int* __restrict__ masks){
    __shared__ float sacc[K_NS][64];
    __shared__ float scnt[K_NS];
    int bh = blockIdx.x;
    int b = bh >> 7;
    int tid = threadIdx.x;
    for (int i = tid; i < K_NS*64; i += 256) (&sacc[0][0])[i] = 0.f;
    if (tid < K_NS) scnt[tid] = 0.f;
    __syncthreads();

    int c = tid & 63, g = tid >> 6;
    float2 st = ((const float2*)g_sct3)[b*64 + c];
    const float* yb = g_y3 + (size_t)bh*K_W*64;
    const int* mrow = masks + (size_t)bh*K_W;
    for (int px = g; px < K_W; px += 4){
        int seg = mrow[px];
        float v = fmaxf(fmaf(st.x, yb[(size_t)px*64 + c], st.y), 0.f);
        atomicAdd(&sacc[seg][c], v);
        if (c == 0) atomicAdd(&scnt[seg], 1.f);
    }
    __syncthreads();
    for (int i = tid; i < K_NS*64; i += 256) atomicAdd(&g_psum[b*K_NS*64 + i], (&sacc[0][0])[i]);
    if (tid < K_NS) atomicAdd(&g_pcnt[b*K_NS + tid], scnt[tid]);
}

// ======================= heads =======================
__global__ void heads(const float* __restrict__ wbox, const float* __restrict__ bbox,
                      const float* __restrict__ wconf, const float* __restrict__ bconf,
                      float* __restrict__ outp){
    int t = threadIdx.x;
    if (t >= K_B*32) return;
    int b = t / 32, o = t % 32, s = o + 1;
    float inv = 1.f / fmaxf(g_pcnt[b*K_NS + s], 1e-4f);
    const float* ps = &g_psum[(b*K_NS + s)*64];
    float pooled[64];
    #pragma unroll
    for (int c = 0; c < 64; c++) pooled[c] = ps[c]*inv;
    #pragma unroll
    for (int k = 0; k < 7; k++){
        float d = bbox[k];
        #pragma unroll
        for (int c = 0; c < 64; c++) d = fmaf(pooled[c], wbox[k*64+c], d);
        outp[(b*32 + o)*7 + k] = d;
    }
    float d = bconf[0];
    #pragma unroll
    for (int c = 0; c < 64; c++) d = fmaf(pooled[c], wconf[c], d);
    outp[K_B*32*7 + b*32 + o] = d;
}

// ======================= launch =======================
extern "C" void kernel_launch(void* const* d_in, const int* in_sizes, int n_in,
                              void* d_out, int out_size){
    const float* x      = (const float*)d_in[0];
    const int*   masks  = (const int*)  d_in[1];
    const float* wcoord = (const float*)d_in[2];
    const float* bcoord = (const float*)d_in[3];
    const float* w1     = (const float*)d_in[4];
    const float* b1     = (const float*)d_in[5];
    const float* gm1    = (const float*)d_in[6];
    const float* bt1    = (const float*)d_in[7];
    const float* w2     = (const float*)d_in[8];
    const float* b2     = (const float*)d_in[9];
    const float* gm2    = (const float*)d_in[10];
    const float* bt2    = (const float*)d_in[11];
    const float* w3     = (const float*)d_in[12];
    const float* b3     = (const float*)d_in[13];
    const float* gm3    = (const float*)d_in[14];
    const float* bt3    = (const float*)d_in[15];
    const float* wbox   = (const float*)d_in[16];
    const float* bbox   = (const float*)d_in[17];
    const float* wconf  = (const float*)d_in[18];
    const float* bconf  = (const float*)d_in[19];
    float* outp = (float*)d_out;

    const int SM1 = 4*10496 + 6*128*80;   // 103424
    const int SM2 = SM1;
    const int SM3 = 4*10496 + 6*64*80;    // 72704
    cudaFuncSetAttribute(conv_hmma<1>, cudaFuncAttributeMaxDynamicSharedMemorySize, SM1);
    cudaFuncSetAttribute(conv_hmma<2>, cudaFuncAttributeMaxDynamicSharedMemorySize, SM2);
    cudaFuncSetAttribute(conv_hmma<3>, cudaFuncAttributeMaxDynamicSharedMemorySize, SM3);

    // conv_hmma<1> kept in the 4th launch slot for ncu capture.
    repack_w<1><<<512,256>>>(w1);
    { dim3 g(9, K_H, K_B); xform1<<<g,256>>>(x, wcoord, bcoord); }
    zero_bufs<<<33,256>>>();
    { dim3 g(K_H, K_B, 2); conv_hmma<1><<<g,256,SM1>>>(b1); }   // <- profiled
    repack_w<2><<<256,256>>>(w2);
    repack_w<3><<<128,256>>>(w3);
    gn_fin<1><<<(K_B*256+255)/256,256>>>(gm1, bt1);
    act_xform<2><<<(int)(((size_t)K_B*K_HW*256)/1024),256>>>();

    { dim3 g(K_H, K_B, 1); conv_hmma<2><<<g,256,SM2>>>(b2); }
    gn_fin<2><<<(K_B*128+255)/256,256>>>(gm2, bt2);
    act_xform<3><<<(int)(((size_t)K_B*K_HW*128)/1024),256>>>();

    { dim3 g(K_H, K_B, 1); conv_hmma<3><<<g,256,SM3>>>(b3); }
    gn_fin<3><<<1,256>>>(gm3, bt3);

    pool_seg<<<K_B*K_H,256>>>(masks);
    heads<<<1,128>>>(wbox, bbox, wconf, bconf, outp);
}